// round 7
// baseline (speedup 1.0000x reference)
#include <cuda_runtime.h>
#include <cstdint>

// ---------------- problem constants ----------------
#define E_NUM     8
#define IN_F      2048
#define OUT_F     2048
#define BM        128
#define BN        256
#define BK        32
#define KCH       (IN_F / BK)      // 64
#define NT_TILES  (OUT_F / BN)     // 8
#define MAXMT     136
#define NTH       256              // 8 warps, 64x64 warp tiles
#define STAGES    2

#define A_FLOATS     (BM * BK)                 // 4096
#define B_FLOATS     (BN * BK)                 // 8192
#define STAGE_FLOATS (A_FLOATS + B_FLOATS)     // 12288
#define SMEM_BYTES   (STAGES * STAGE_FLOATS * 4)  // 98304

// ---------------- ptx helpers (base ISA only) ------------
static __device__ __forceinline__ uint32_t smem_u32(const void* p) {
    uint32_t a;
    asm("{ .reg .u64 t; cvta.to.shared.u64 t, %1; cvt.u32.u64 %0, t; }" : "=r"(a) : "l"(p));
    return a;
}

static __device__ __forceinline__ uint32_t tf32_rna(float f) {
    uint32_t r;
    asm("cvt.rna.tf32.f32 %0, %1;" : "=r"(r) : "f"(f));
    return r;
}

static __device__ __forceinline__ void sts128(uint32_t addr, uint32_t x, uint32_t y,
                                              uint32_t z, uint32_t w) {
    asm volatile("st.shared.v4.b32 [%0], {%1, %2, %3, %4};"
                 :: "r"(addr), "r"(x), "r"(y), "r"(z), "r"(w) : "memory");
}

static __device__ __forceinline__ void mma8(float* c, const uint32_t* a, const uint32_t* b) {
    asm volatile(
        "mma.sync.aligned.m16n8k8.row.col.f32.tf32.tf32.f32 "
        "{%0,%1,%2,%3}, {%4,%5,%6,%7}, {%8,%9}, {%0,%1,%2,%3};"
        : "+f"(c[0]), "+f"(c[1]), "+f"(c[2]), "+f"(c[3])
        : "r"(a[0]), "r"(a[1]), "r"(a[2]), "r"(a[3]), "r"(b[0]), "r"(b[1]));
}

static __device__ __forceinline__ long long load_off(const int* p, int i, bool is64) {
    if (is64) return ((const long long*)p)[i];
    return (long long)p[i];
}

__global__ void __launch_bounds__(NTH, 1)
moe_mma_kernel(const float* __restrict__ X,
               const int*   __restrict__ offs_raw,
               const float* __restrict__ W,
               const float* __restrict__ Bias,
               float*       __restrict__ Y)
{
    const int tid  = threadIdx.x;
    const int lane = tid & 31;
    const int wid  = tid >> 5;
    const int wm   = wid >> 2;   // 0..1 : 64-row slab
    const int wn   = wid & 3;    // 0..3 : 64-col slab
    const int n0   = blockIdx.x * BN;

    // ---- flat m-tile -> (expert, row range) ----
    const bool is64 = ((offs_raw[1] | offs_raw[3] | offs_raw[5] | offs_raw[7]) == 0);
    int e = -1;
    long long row0 = 0, rend = 0;
    {
        int rem = blockIdx.y;
        long long lo = load_off(offs_raw, 0, is64);
        #pragma unroll
        for (int i = 0; i < E_NUM; i++) {
            long long hi = load_off(offs_raw, i + 1, is64);
            int t = (int)((hi - lo + (BM - 1)) >> 7);
            if (e < 0 && rem < t) { e = i; row0 = lo + ((long long)rem << 7); rend = hi; }
            if (e < 0) rem -= t;
            lo = hi;
        }
    }
    if (e < 0) return;  // surplus CTA, uniform exit
    const int rows = (int)(((rend - row0) < BM) ? (rend - row0) : BM);

    extern __shared__ float smf[];
    const uint32_t smem_base = smem_u32(smf);
    const uint32_t* __restrict__ smu = (const uint32_t*)smf;

    // ---- staging geometry: 256 threads, 8 per 32-float row -> 32 rows/pass ----
    const int grow = tid >> 3;          // 0..31 base row
    const int gc4  = tid & 7;           // 16B column group
    // byte offset of this thread's vec4 slot in row `grow` (XOR-4 swizzle);
    // pass p adds p*32 rows = p*4096 bytes (row&7 invariant since 32%8==0)
    const uint32_t asm0 = (uint32_t)(grow * 32 + ((gc4 * 4) ^ ((grow & 7) * 4))) * 4u;

    bool aval[4];
    #pragma unroll
    for (int p = 0; p < 4; p++) aval[p] = (grow + 32 * p) < rows;

    const float* Xb = X + (size_t)(row0 + grow) * IN_F + gc4 * 4;          // + p*32*IN_F + kc*BK
    const float* Wb = W + ((size_t)e * OUT_F + n0 + grow) * IN_F + gc4 * 4;

    // ---- staging registers (hold kc+1 data during compute of kc) ----
    float4 sa[4], sb[8];

    auto ldg_stage = [&](int kc) {
        const size_t ko = (size_t)kc * BK;
        #pragma unroll
        for (int p = 0; p < 4; p++)
            sa[p] = aval[p] ? __ldg((const float4*)(Xb + ko + (size_t)p * 32 * IN_F))
                            : make_float4(0.f, 0.f, 0.f, 0.f);
        #pragma unroll
        for (int p = 0; p < 8; p++)
            sb[p] = __ldg((const float4*)(Wb + ko + (size_t)p * 32 * IN_F));
    };

    // ---- accumulators: warp tile 64x64 ----
    float acc[4][8][4];
    #pragma unroll
    for (int mi = 0; mi < 4; mi++)
        #pragma unroll
        for (int nj = 0; nj < 8; nj++)
            #pragma unroll
            for (int q = 0; q < 4; q++) acc[mi][nj][q] = 0.0f;

    const int lr  = lane >> 2;               // 0..7
    const int lc  = lane & 3;                // 0..3
    const uint32_t fsw = (uint32_t)(lr * 4); // fragment swizzle term

    // ---- prologue: stage kc=0 into buf0, prefetch kc=1 into regs ----
    ldg_stage(0);
    {
        uint32_t ab = smem_base;                  // buf0
        uint32_t bb = ab + A_FLOATS * 4;
        #pragma unroll
        for (int p = 0; p < 4; p++) {
            float4 v = sa[p];
            sts128(ab + asm0 + p * 4096u,
                   tf32_rna(v.x), tf32_rna(v.y), tf32_rna(v.z), tf32_rna(v.w));
        }
        #pragma unroll
        for (int p = 0; p < 8; p++) {
            float4 v = sb[p];
            sts128(bb + asm0 + p * 4096u,
                   tf32_rna(v.x), tf32_rna(v.y), tf32_rna(v.z), tf32_rna(v.w));
        }
    }
    ldg_stage(1);
    __syncthreads();

    // ---- mainloop: smem holds pre-rounded tf32; consumer is LDS -> MMA ----
    for (int kc = 0; kc < KCH; kc++) {
        const uint32_t* As = smu + (kc & 1) * STAGE_FLOATS;
        const uint32_t* Bs = As + A_FLOATS;
        const bool do_sts  = (kc + 1) < KCH;
        const uint32_t ab  = smem_base + (uint32_t)((kc + 1) & 1) * (STAGE_FLOATS * 4);
        const uint32_t bb  = ab + A_FLOATS * 4;

        #pragma unroll
        for (int ks = 0; ks < 4; ks++) {
            const int k0 = ks * 8;
            uint32_t a[4][4], b[8][2];
            #pragma unroll
            for (int mi = 0; mi < 4; mi++) {
                int r = wm * 64 + mi * 16 + lr;
                a[mi][0] = As[r * 32       + ((k0 + lc)     ^ fsw)];
                a[mi][1] = As[(r + 8) * 32 + ((k0 + lc)     ^ fsw)];
                a[mi][2] = As[r * 32       + ((k0 + 4 + lc) ^ fsw)];
                a[mi][3] = As[(r + 8) * 32 + ((k0 + 4 + lc) ^ fsw)];
            }
            #pragma unroll
            for (int nj = 0; nj < 8; nj++) {
                int n = wn * 64 + nj * 8 + lr;
                b[nj][0] = Bs[n * 32 + ((k0 + lc)     ^ fsw)];
                b[nj][1] = Bs[n * 32 + ((k0 + 4 + lc) ^ fsw)];
            }

            // interleave 3 of the 12 producer CVT+STS ops (next kc's data)
            if (do_sts) {
                #pragma unroll
                for (int j = 3 * ks; j < 3 * ks + 3; j++) {
                    if (j < 4) {
                        float4 v = sa[j];
                        sts128(ab + asm0 + (uint32_t)j * 4096u,
                               tf32_rna(v.x), tf32_rna(v.y), tf32_rna(v.z), tf32_rna(v.w));
                    } else {
                        float4 v = sb[j - 4];
                        sts128(bb + asm0 + (uint32_t)(j - 4) * 4096u,
                               tf32_rna(v.x), tf32_rna(v.y), tf32_rna(v.z), tf32_rna(v.w));
                    }
                }
            }

            #pragma unroll
            for (int mi = 0; mi < 4; mi++)
                #pragma unroll
                for (int nj = 0; nj < 8; nj++)
                    mma8(acc[mi][nj], a[mi], b[nj]);
        }

        if (kc + 2 < KCH) ldg_stage(kc + 2);   // ~1 full compute phase of latency slack
        __syncthreads();
    }

    // ---- epilogue: bias add + float2 stores ----
    #pragma unroll
    for (int nj = 0; nj < 8; nj++) {
        const int gc = n0 + wn * 64 + nj * 8 + lc * 2;
        const float b0 = __ldg(Bias + (size_t)e * OUT_F + gc);
        const float b1 = __ldg(Bias + (size_t)e * OUT_F + gc + 1);
        #pragma unroll
        for (int mi = 0; mi < 4; mi++) {
            const int gr = wm * 64 + mi * 16 + lr;
            if (gr < rows) {
                float2 v;
                v.x = acc[mi][nj][0] + b0;
                v.y = acc[mi][nj][1] + b1;
                *(float2*)(Y + (size_t)(row0 + gr) * OUT_F + gc) = v;
            }
            if (gr + 8 < rows) {
                float2 v;
                v.x = acc[mi][nj][2] + b0;
                v.y = acc[mi][nj][3] + b1;
                *(float2*)(Y + (size_t)(row0 + gr + 8) * OUT_F + gc) = v;
            }
        }
    }
}

extern "C" void kernel_launch(void* const* d_in, const int* in_sizes, int n_in,
                              void* d_out, int out_size) {
    const float* X    = (const float*)d_in[0];
    const int*   offs = (const int*)d_in[1];
    const float* W    = (const float*)d_in[2];
    const float* Bias = (const float*)d_in[3];
    float*       Y    = (float*)d_out;

    cudaFuncSetAttribute(moe_mma_kernel,
                         cudaFuncAttributeMaxDynamicSharedMemorySize, SMEM_BYTES);
    dim3 grid(NT_TILES, MAXMT);
    moe_mma_kernel<<<grid, NTH, SMEM_BYTES>>>(X, offs, W, Bias, Y);
}

// round 8
// speedup vs baseline: 1.1635x; 1.1635x over previous
#include <cuda_runtime.h>
#include <cstdint>

// ---------------- problem constants ----------------
#define E_NUM     8
#define IN_F      2048
#define OUT_F     2048
#define TOTAL_T   16384
#define BM        128
#define BN        256
#define BK        32
#define KCH       (IN_F / BK)      // 64
#define NT_TILES  (OUT_F / BN)     // 8
#define MAXMT     136
#define NTH       256
#define STAGES    3

#define A_FLOATS     (BM * BK)                 // 4096
#define B_FLOATS     (BN * BK)                 // 8192
#define STAGE_FLOATS (A_FLOATS + B_FLOATS)     // 12288
#define SMEM_BYTES   (STAGES * STAGE_FLOATS * 4)  // 147456

// ---------------- scratch: pre-rounded tf32 copies of X and W ----------------
__device__ static uint32_t g_Xr[TOTAL_T * IN_F];          // 128 MB
__device__ static uint32_t g_Wr[E_NUM * OUT_F * IN_F];    // 128 MB

// ---------------- ptx helpers (base ISA only) ------------
static __device__ __forceinline__ uint32_t smem_u32(const void* p) {
    uint32_t a;
    asm("{ .reg .u64 t; cvta.to.shared.u64 t, %1; cvt.u32.u64 %0, t; }" : "=r"(a) : "l"(p));
    return a;
}

static __device__ __forceinline__ uint32_t tf32_rna(float f) {
    uint32_t r;
    asm("cvt.rna.tf32.f32 %0, %1;" : "=r"(r) : "f"(f));
    return r;
}

static __device__ __forceinline__ void cp16(uint32_t dst, const void* src, uint32_t srcsz) {
    asm volatile("cp.async.cg.shared.global [%0], [%1], 16, %2;"
                 :: "r"(dst), "l"(src), "r"(srcsz) : "memory");
}

static __device__ __forceinline__ void cp_commit() {
    asm volatile("cp.async.commit_group;" ::: "memory");
}

static __device__ __forceinline__ void cp_wait1() {
    asm volatile("cp.async.wait_group 1;" ::: "memory");
}

static __device__ __forceinline__ void mma8(float* c, const uint32_t* a, const uint32_t* b) {
    asm volatile(
        "mma.sync.aligned.m16n8k8.row.col.f32.tf32.tf32.f32 "
        "{%0,%1,%2,%3}, {%4,%5,%6,%7}, {%8,%9}, {%0,%1,%2,%3};"
        : "+f"(c[0]), "+f"(c[1]), "+f"(c[2]), "+f"(c[3])
        : "r"(a[0]), "r"(a[1]), "r"(a[2]), "r"(a[3]), "r"(b[0]), "r"(b[1]));
}

static __device__ __forceinline__ long long load_off(const int* p, int i, bool is64) {
    if (is64) return ((const long long*)p)[i];
    return (long long)p[i];
}

// ---------------- pre-pass: fp32 -> tf32(RNA) rounding into scratch ----------
__global__ void __launch_bounds__(256, 4)
cvt_x_kernel(const float4* __restrict__ src) {
    const int i = blockIdx.x * 256 + threadIdx.x;   // grid sized exactly
    float4 v = __ldg(src + i);
    uint4 o;
    o.x = tf32_rna(v.x); o.y = tf32_rna(v.y); o.z = tf32_rna(v.z); o.w = tf32_rna(v.w);
    ((uint4*)g_Xr)[i] = o;
}

__global__ void __launch_bounds__(256, 4)
cvt_w_kernel(const float4* __restrict__ src) {
    const int i = blockIdx.x * 256 + threadIdx.x;
    float4 v = __ldg(src + i);
    uint4 o;
    o.x = tf32_rna(v.x); o.y = tf32_rna(v.y); o.z = tf32_rna(v.z); o.w = tf32_rna(v.w);
    ((uint4*)g_Wr)[i] = o;
}

// ---------------- main grouped-GEMM kernel (consumer: LDS -> MMA) ------------
__global__ void __launch_bounds__(NTH, 1)
moe_mma_kernel(const int*   __restrict__ offs_raw,
               const float* __restrict__ Bias,
               float*       __restrict__ Y)
{
    const int tid  = threadIdx.x;
    const int lane = tid & 31;
    const int wid  = tid >> 5;
    const int wm   = wid >> 2;   // 0..1 : 64-row slab
    const int wn   = wid & 3;    // 0..3 : 64-col slab
    const int n0   = blockIdx.x * BN;
    const int stg2 = (wid >> 2) << 1;   // 0 or 2: ks-order stagger between co-SMSP warps

    const float* X = (const float*)g_Xr;
    const float* W = (const float*)g_Wr;

    // ---- flat m-tile -> (expert, row range) ----
    const bool is64 = ((offs_raw[1] | offs_raw[3] | offs_raw[5] | offs_raw[7]) == 0);
    int e = -1;
    long long row0 = 0, rend = 0;
    {
        int rem = blockIdx.y;
        long long lo = load_off(offs_raw, 0, is64);
        #pragma unroll
        for (int i = 0; i < E_NUM; i++) {
            long long hi = load_off(offs_raw, i + 1, is64);
            int t = (int)((hi - lo + (BM - 1)) >> 7);
            if (e < 0 && rem < t) { e = i; row0 = lo + ((long long)rem << 7); rend = hi; }
            if (e < 0) rem -= t;
            lo = hi;
        }
    }
    if (e < 0) return;  // surplus CTA, uniform exit
    const int rows = (int)(((rend - row0) < BM) ? (rend - row0) : BM);

    extern __shared__ float smf[];
    const uint32_t smem_base = smem_u32(smf);
    const uint32_t* __restrict__ smu = (const uint32_t*)smf;

    // ---- staging precompute (lane-constant XOR-4 swizzle) ----
    const int grow = tid >> 3;          // 0..31 base row
    const int gc4  = tid & 7;           // 16B column group
    const uint32_t a_sw = (uint32_t)((gc4 * 4) ^ ((grow & 7) * 4));

    const float* agp[4]; uint32_t asz[4]; uint32_t asmoff[4];
    #pragma unroll
    for (int p = 0; p < 4; p++) {
        int ar = grow + 32 * p;
        bool v = ar < rows;
        agp[p]    = X + (size_t)(row0 + (v ? ar : 0)) * IN_F + gc4 * 4;
        asz[p]    = v ? 16u : 0u;
        asmoff[p] = (uint32_t)(ar * 32) * 4u + a_sw * 4u;
    }
    const float* bgp[8]; uint32_t bsmoff[8];
    #pragma unroll
    for (int p = 0; p < 8; p++) {
        int br = grow + 32 * p;
        bgp[p]    = W + ((size_t)e * OUT_F + n0 + br) * IN_F + gc4 * 4;
        bsmoff[p] = (uint32_t)(br * 32) * 4u + a_sw * 4u;
    }

    // ---- accumulators: warp tile 64x64 ----
    float acc[4][8][4];
    #pragma unroll
    for (int mi = 0; mi < 4; mi++)
        #pragma unroll
        for (int nj = 0; nj < 8; nj++)
            #pragma unroll
            for (int q = 0; q < 4; q++) acc[mi][nj][q] = 0.0f;

    auto load_stage = [&](int kc, int sidx) {
        if (kc < KCH) {
            uint32_t ab = smem_base + (uint32_t)sidx * (STAGE_FLOATS * 4);
            uint32_t bb = ab + A_FLOATS * 4;
            const uint32_t koff = (uint32_t)kc * BK;
            #pragma unroll
            for (int p = 0; p < 4; p++) cp16(ab + asmoff[p], agp[p] + koff, asz[p]);
            #pragma unroll
            for (int p = 0; p < 8; p++) cp16(bb + bsmoff[p], bgp[p] + koff, 16u);
        }
        cp_commit();
    };

    const int lr  = lane >> 2;               // 0..7
    const int lc  = lane & 3;                // 0..3
    const uint32_t fsw = (uint32_t)(lr * 4); // fragment swizzle term

    load_stage(0, 0);
    load_stage(1, 1);

    // double-buffered fragment registers (no CVT anywhere: smem is tf32 already)
    uint32_t af[2][4][4], bf[2][8][2];

    int sidx = 0, pidx = 2;
    for (int kc = 0; kc < KCH; kc++) {
        cp_wait1();
        __syncthreads();
        load_stage(kc + 2, pidx);

        const uint32_t* As = smu + sidx * STAGE_FLOATS;
        const uint32_t* Bs = As + A_FLOATS;

        auto load_frags = [&](int ks, int bi) {
            const int k0 = ks * 8;
            #pragma unroll
            for (int mi = 0; mi < 4; mi++) {
                int r = wm * 64 + mi * 16 + lr;
                af[bi][mi][0] = As[r * 32       + ((k0 + lc)     ^ fsw)];
                af[bi][mi][1] = As[(r + 8) * 32 + ((k0 + lc)     ^ fsw)];
                af[bi][mi][2] = As[r * 32       + ((k0 + 4 + lc) ^ fsw)];
                af[bi][mi][3] = As[(r + 8) * 32 + ((k0 + 4 + lc) ^ fsw)];
            }
            #pragma unroll
            for (int nj = 0; nj < 8; nj++) {
                int n = wn * 64 + nj * 8 + lr;
                bf[bi][nj][0] = Bs[n * 32 + ((k0 + lc)     ^ fsw)];
                bf[bi][nj][1] = Bs[n * 32 + ((k0 + 4 + lc) ^ fsw)];
            }
        };

        // ks order staggered between the two warps sharing an SMSP
        load_frags(0 ^ stg2, 0);
        #pragma unroll
        for (int i = 0; i < 4; i++) {
            const int cur = i & 1;
            if (i < 3) load_frags((i + 1) ^ stg2, cur ^ 1);
            #pragma unroll
            for (int mi = 0; mi < 4; mi++)
                #pragma unroll
                for (int nj = 0; nj < 8; nj++)
                    mma8(acc[mi][nj], af[cur][mi], bf[cur][nj]);
        }

        sidx = (sidx == STAGES - 1) ? 0 : sidx + 1;
        pidx = (pidx == STAGES - 1) ? 0 : pidx + 1;
    }

    // ---- epilogue: bias add + float2 stores ----
    #pragma unroll
    for (int nj = 0; nj < 8; nj++) {
        const int gc = n0 + wn * 64 + nj * 8 + lc * 2;
        const float b0 = __ldg(Bias + (size_t)e * OUT_F + gc);
        const float b1 = __ldg(Bias + (size_t)e * OUT_F + gc + 1);
        #pragma unroll
        for (int mi = 0; mi < 4; mi++) {
            const int gr = wm * 64 + mi * 16 + lr;
            if (gr < rows) {
                float2 v;
                v.x = acc[mi][nj][0] + b0;
                v.y = acc[mi][nj][1] + b1;
                *(float2*)(Y + (size_t)(row0 + gr) * OUT_F + gc) = v;
            }
            if (gr + 8 < rows) {
                float2 v;
                v.x = acc[mi][nj][2] + b0;
                v.y = acc[mi][nj][3] + b1;
                *(float2*)(Y + (size_t)(row0 + gr + 8) * OUT_F + gc) = v;
            }
        }
    }
}

extern "C" void kernel_launch(void* const* d_in, const int* in_sizes, int n_in,
                              void* d_out, int out_size) {
    const float* X    = (const float*)d_in[0];
    const int*   offs = (const int*)d_in[1];
    const float* W    = (const float*)d_in[2];
    const float* Bias = (const float*)d_in[3];
    float*       Y    = (float*)d_out;

    // pre-pass: round inputs to tf32 once (RNA), into __device__ scratch
    {
        const int n4x = (TOTAL_T * IN_F) / 4;
        cvt_x_kernel<<<n4x / 256, 256>>>((const float4*)X);
        const int n4w = (E_NUM * OUT_F * IN_F) / 4;
        cvt_w_kernel<<<n4w / 256, 256>>>((const float4*)W);
    }

    cudaFuncSetAttribute(moe_mma_kernel,
                         cudaFuncAttributeMaxDynamicSharedMemorySize, SMEM_BYTES);
    dim3 grid(NT_TILES, MAXMT);
    moe_mma_kernel<<<grid, NTH, SMEM_BYTES>>>(offs, Bias, Y);
}

// round 9
// speedup vs baseline: 1.1848x; 1.0182x over previous
#include <cuda_runtime.h>
#include <cstdint>

// ---------------- problem constants ----------------
#define E_NUM     8
#define IN_F      2048
#define OUT_F     2048
#define TOTAL_T   16384
#define BM        128
#define BN        256
#define BK        32
#define KCH       (IN_F / BK)      // 64
#define NT_TILES  (OUT_F / BN)     // 8
#define MAXMT     136
#define NTH       256
#define STAGES    3

#define A_FLOATS   (BM * BK)                   // 4096 (= 1024 quads)
#define B_FLOATS   (BN * BK)                   // 8192 (= 2048 quads)
#define STAGE_B    ((A_FLOATS + B_FLOATS) * 4) // 49152
#define SMEM_BYTES (STAGES * STAGE_B)          // 147456

// ---------------- fragment-major scratch ----------------
// X packed per m-tile:  [mtile][kc][ks(4)][mi(4)][wm(2)][lane(32)] x uint4
// W packed per n-tile:  [e*8+nt][kc][ks(4)][njp(4)][wn(4)][lane(32)] x uint4
__device__ static uint32_t g_Xr[(size_t)MAXMT * KCH * A_FLOATS];          // ~142.6 MB
__device__ static uint32_t g_Wr[(size_t)E_NUM * NT_TILES * KCH * B_FLOATS]; // 128 MB

// ---------------- ptx helpers (base ISA only) ------------
static __device__ __forceinline__ uint32_t smem_u32(const void* p) {
    uint32_t a;
    asm("{ .reg .u64 t; cvta.to.shared.u64 t, %1; cvt.u32.u64 %0, t; }" : "=r"(a) : "l"(p));
    return a;
}

static __device__ __forceinline__ uint32_t tf32_rna(float f) {
    uint32_t r;
    asm("cvt.rna.tf32.f32 %0, %1;" : "=r"(r) : "f"(f));
    return r;
}

static __device__ __forceinline__ void cp16(uint32_t dst, const void* src) {
    asm volatile("cp.async.cg.shared.global [%0], [%1], 16;"
                 :: "r"(dst), "l"(src) : "memory");
}

static __device__ __forceinline__ void cp_commit() {
    asm volatile("cp.async.commit_group;" ::: "memory");
}

static __device__ __forceinline__ void cp_wait1() {
    asm volatile("cp.async.wait_group 1;" ::: "memory");
}

static __device__ __forceinline__ void lds128(uint32_t* r, uint32_t addr) {
    asm volatile("ld.shared.v4.b32 {%0, %1, %2, %3}, [%4];"
                 : "=r"(r[0]), "=r"(r[1]), "=r"(r[2]), "=r"(r[3]) : "r"(addr));
}

static __device__ __forceinline__ void mma8(float* c, const uint32_t* a, const uint32_t* b) {
    asm volatile(
        "mma.sync.aligned.m16n8k8.row.col.f32.tf32.tf32.f32 "
        "{%0,%1,%2,%3}, {%4,%5,%6,%7}, {%8,%9}, {%0,%1,%2,%3};"
        : "+f"(c[0]), "+f"(c[1]), "+f"(c[2]), "+f"(c[3])
        : "r"(a[0]), "r"(a[1]), "r"(a[2]), "r"(a[3]), "r"(b[0]), "r"(b[1]));
}

static __device__ __forceinline__ long long load_off(const int* p, int i, bool is64) {
    if (is64) return ((const long long*)p)[i];
    return (long long)p[i];
}

// shared m-tile scan: flat tile id -> (expert, row0, rows); e<0 if surplus
static __device__ __forceinline__ void tile_scan(const int* offs_raw, int mtile,
                                                 int& e, long long& row0, int& rows) {
    const bool is64 = ((offs_raw[1] | offs_raw[3] | offs_raw[5] | offs_raw[7]) == 0);
    e = -1; row0 = 0;
    long long rend = 0;
    int rem = mtile;
    long long lo = load_off(offs_raw, 0, is64);
    #pragma unroll
    for (int i = 0; i < E_NUM; i++) {
        long long hi = load_off(offs_raw, i + 1, is64);
        int t = (int)((hi - lo + (BM - 1)) >> 7);
        if (e < 0 && rem < t) { e = i; row0 = lo + ((long long)rem << 7); rend = hi; }
        if (e < 0) rem -= t;
        lo = hi;
    }
    rows = (e < 0) ? 0 : (int)(((rend - row0) < BM) ? (rend - row0) : BM);
}

// ---------------- pre-pass: pack X into fragment-major tf32 ----------------
// grid (16, MAXMT): x = 4-kc slice, y = m-tile. Zero-pads rows >= rows.
__global__ void __launch_bounds__(256, 2)
pack_x_kernel(const float* __restrict__ X, const int* __restrict__ offs_raw) {
    const int mtile = blockIdx.y;
    int e; long long row0; int rows;
    tile_scan(offs_raw, mtile, e, row0, rows);
    if (e < 0) return;

    const int tid = threadIdx.x;
    #pragma unroll
    for (int kcL = 0; kcL < 4; kcL++) {
        const int kc = blockIdx.x * 4 + kcL;
        #pragma unroll
        for (int j = 0; j < 4; j++) {
            const int idx  = tid + j * 256;        // quad index 0..1023
            const int lane = idx & 31;
            const int wm   = (idx >> 5) & 1;
            const int mi   = (idx >> 6) & 3;
            const int ks   = (idx >> 8) & 3;
            const int r    = wm * 64 + mi * 16 + (lane >> 2);
            const int c    = kc * BK + ks * 8 + (lane & 3);
            uint4 o = make_uint4(0u, 0u, 0u, 0u);
            if (r < rows) {
                const float* p = X + (size_t)(row0 + r) * IN_F + c;
                o.x = tf32_rna(p[0]);
                o.z = tf32_rna(p[4]);
            }
            if (r + 8 < rows) {
                const float* p = X + (size_t)(row0 + r + 8) * IN_F + c;
                o.y = tf32_rna(p[0]);
                o.w = tf32_rna(p[4]);
            }
            ((uint4*)g_Xr)[((size_t)mtile * KCH + kc) * 1024 + idx] = o;
        }
    }
}

// ---------------- pre-pass: pack W into fragment-major tf32 ----------------
// grid (16, 64): x = 4-kc slice, y = e*8+nt.
__global__ void __launch_bounds__(256, 2)
pack_w_kernel(const float* __restrict__ W) {
    const int ent = blockIdx.y;                    // e*8 + nt
    const int ebase_n = (ent & 7) * BN;            // n-tile offset within expert
    const float* We = W + (size_t)(ent >> 3) * OUT_F * IN_F;

    const int tid = threadIdx.x;
    #pragma unroll
    for (int kcL = 0; kcL < 4; kcL++) {
        const int kc = blockIdx.x * 4 + kcL;
        #pragma unroll
        for (int j = 0; j < 8; j++) {
            const int idx  = tid + j * 256;        // quad index 0..2047
            const int lane = idx & 31;
            const int wn   = (idx >> 5) & 3;
            const int njp  = (idx >> 7) & 3;
            const int ks   = (idx >> 9) & 3;
            const int n    = ebase_n + wn * 64 + njp * 16 + (lane >> 2);
            const int c    = kc * BK + ks * 8 + (lane & 3);
            const float* p0 = We + (size_t)n * IN_F + c;
            const float* p1 = p0 + 8 * IN_F;
            uint4 o;
            o.x = tf32_rna(p0[0]);
            o.y = tf32_rna(p0[4]);
            o.z = tf32_rna(p1[0]);
            o.w = tf32_rna(p1[4]);
            ((uint4*)g_Wr)[((size_t)ent * KCH + kc) * 2048 + idx] = o;
        }
    }
}

// ---------------- main grouped-GEMM kernel: LDS.128 -> MMA ----------------
__global__ void __launch_bounds__(NTH, 1)
moe_mma_kernel(const int*   __restrict__ offs_raw,
               const float* __restrict__ Bias,
               float*       __restrict__ Y)
{
    const int tid  = threadIdx.x;
    const int lane = tid & 31;
    const int wid  = tid >> 5;
    const int wm   = wid >> 2;   // 0..1
    const int wn   = wid & 3;    // 0..3
    const int n0   = blockIdx.x * BN;

    int e; long long row0; int rows;
    tile_scan(offs_raw, blockIdx.y, e, row0, rows);
    if (e < 0) return;

    extern __shared__ float smf[];
    const uint32_t smem_base = smem_u32(smf);

    // producer: linear fragment-major blocks
    const uint32_t* gA = g_Xr + (size_t)blockIdx.y * KCH * A_FLOATS;
    const uint32_t* gB = g_Wr + ((size_t)e * NT_TILES + blockIdx.x) * KCH * B_FLOATS;

    auto load_stage = [&](int kc, int sidx) {
        if (kc < KCH) {
            const uint32_t ab = smem_base + (uint32_t)sidx * STAGE_B;
            const uint32_t bb = ab + A_FLOATS * 4;
            const uint32_t* ga = gA + (size_t)kc * A_FLOATS;
            const uint32_t* gb = gB + (size_t)kc * B_FLOATS;
            #pragma unroll
            for (int j = 0; j < 4; j++)
                cp16(ab + (uint32_t)(tid + j * 256) * 16u, ga + (size_t)(tid + j * 256) * 4);
            #pragma unroll
            for (int j = 0; j < 8; j++)
                cp16(bb + (uint32_t)(tid + j * 256) * 16u, gb + (size_t)(tid + j * 256) * 4);
        }
        cp_commit();
    };

    // ---- accumulators: warp tile 64x64 ----
    float acc[4][8][4];
    #pragma unroll
    for (int mi = 0; mi < 4; mi++)
        #pragma unroll
        for (int nj = 0; nj < 8; nj++)
            #pragma unroll
            for (int q = 0; q < 4; q++) acc[mi][nj][q] = 0.0f;

    // consumer base offsets (bytes within stage)
    const uint32_t abw = (uint32_t)(wm * 32 + lane) * 16u;   // into A block
    const uint32_t bbw = (uint32_t)(wn * 32 + lane) * 16u;   // into B block

    load_stage(0, 0);
    load_stage(1, 1);

    uint32_t af[2][4][4], bq[2][4][4];   // double-buffered fragment quads

    int sidx = 0, pidx = 2;
    for (int kc = 0; kc < KCH; kc++) {
        cp_wait1();
        __syncthreads();
        load_stage(kc + 2, pidx);

        const uint32_t As = smem_base + (uint32_t)sidx * STAGE_B;
        const uint32_t Bs = As + A_FLOATS * 4;

        auto load_frags = [&](int ks, int bi) {
            #pragma unroll
            for (int mi = 0; mi < 4; mi++)
                lds128(af[bi][mi], As + abw + (uint32_t)(ks * 4 + mi) * 1024u);
            #pragma unroll
            for (int njp = 0; njp < 4; njp++)
                lds128(bq[bi][njp], Bs + bbw + (uint32_t)(ks * 4 + njp) * 2048u);
        };

        load_frags(0, 0);
        #pragma unroll
        for (int ks = 0; ks < 4; ks++) {
            const int cur = ks & 1;
            if (ks < 3) load_frags(ks + 1, cur ^ 1);
            #pragma unroll
            for (int mi = 0; mi < 4; mi++) {
                #pragma unroll
                for (int njp = 0; njp < 4; njp++) {
                    mma8(acc[mi][2 * njp],     af[cur][mi], &bq[cur][njp][0]);
                    mma8(acc[mi][2 * njp + 1], af[cur][mi], &bq[cur][njp][2]);
                }
            }
        }

        sidx = (sidx == STAGES - 1) ? 0 : sidx + 1;
        pidx = (pidx == STAGES - 1) ? 0 : pidx + 1;
    }

    // ---- epilogue: bias add + float2 stores ----
    const int lr = lane >> 2;
    const int lc = lane & 3;
    #pragma unroll
    for (int nj = 0; nj < 8; nj++) {
        const int gc = n0 + wn * 64 + nj * 8 + lc * 2;
        const float b0 = __ldg(Bias + (size_t)e * OUT_F + gc);
        const float b1 = __ldg(Bias + (size_t)e * OUT_F + gc + 1);
        #pragma unroll
        for (int mi = 0; mi < 4; mi++) {
            const int gr = wm * 64 + mi * 16 + lr;
            if (gr < rows) {
                float2 v;
                v.x = acc[mi][nj][0] + b0;
                v.y = acc[mi][nj][1] + b1;
                *(float2*)(Y + (size_t)(row0 + gr) * OUT_F + gc) = v;
            }
            if (gr + 8 < rows) {
                float2 v;
                v.x = acc[mi][nj][2] + b0;
                v.y = acc[mi][nj][3] + b1;
                *(float2*)(Y + (size_t)(row0 + gr + 8) * OUT_F + gc) = v;
            }
        }
    }
}

extern "C" void kernel_launch(void* const* d_in, const int* in_sizes, int n_in,
                              void* d_out, int out_size) {
    const float* X    = (const float*)d_in[0];
    const int*   offs = (const int*)d_in[1];
    const float* W    = (const float*)d_in[2];
    const float* Bias = (const float*)d_in[3];
    float*       Y    = (float*)d_out;

    pack_x_kernel<<<dim3(16, MAXMT), 256>>>(X, offs);
    pack_w_kernel<<<dim3(16, E_NUM * NT_TILES), 256>>>(W);

    cudaFuncSetAttribute(moe_mma_kernel,
                         cudaFuncAttributeMaxDynamicSharedMemorySize, SMEM_BYTES);
    dim3 grid(NT_TILES, MAXMT);
    moe_mma_kernel<<<grid, NTH, SMEM_BYTES>>>(offs, Bias, Y);
}